// round 12
// baseline (speedup 1.0000x reference)
#include <cuda_runtime.h>
#include <cuda_bf16.h>
#include <cstdint>

// ---- problem constants ----
#define T1n 128
#define T2n 512
#define TPn 8
#define Hn  16
#define Kn  4
#define Cn  129   // 2*K*H+1
#define Dn  256

// ---- device scratch ----
__device__ float  g_e2T[Dn * T2n];            // e2 transposed (unnormalized)
__device__ float  g_val[T1n * T2n];
__device__ uint2  g_pack[T1n * TPn * T2n];    // bucket-sorted compacted {awb, ap}
__device__ int    g_bs[T1n * TPn * 17];       // bucket starts (bs[16] = cnt)
__device__ float2 g_WN[T1n * TPn * 16];       // per-bucket {sum aw, (float)count}
__device__ float  g_SA[T1n * TPn];            // sum m*A^2
__device__ float  g_L64[T1n];                 // loss for c == sta

// ---------------------------------------------------------------------------
// K0: transpose e2 [512][256] -> g_e2T [256][512] via 32x32 smem tiles.
// ---------------------------------------------------------------------------
__global__ __launch_bounds__(256) void k_t2(const float* __restrict__ e2) {
    int j0 = blockIdx.x * 32;       // 16 tiles
    int k0 = blockIdx.y * 32;       // 8 tiles
    int tx = threadIdx.x;           // 0..31
    int ty = threadIdx.y;           // 0..7
    __shared__ float s[32][33];
    #pragma unroll
    for (int u = 0; u < 4; u++) {
        int row = ty + u * 8;
        s[row][tx] = e2[(j0 + row) * Dn + k0 + tx];      // coalesced read
    }
    __syncthreads();
    #pragma unroll
    for (int u = 0; u < 4; u++) {
        int row = ty + u * 8;
        g_e2T[(k0 + row) * T2n + j0 + tx] = s[tx][row];  // coalesced write
    }
}

// ---------------------------------------------------------------------------
// K1: val_v[i][j]. Grid (32,4); 256 threads = (kh = tid>>7, jl = tid&127).
//   e1 (4 rows) normalized into k-major smem (one LDS.128 = 4 row values).
//   Each half-block accumulates k in [kh*128, kh*128+128) with coalesced
//   LDG from g_e2T; e2 ssq folded in. Halves combined via smem.
// ---------------------------------------------------------------------------
__global__ __launch_bounds__(256) void k_val(const float* __restrict__ e1) {
    int i0 = blockIdx.x * 4;
    int j0 = blockIdx.y * 128;
    int tid = threadIdx.x;
    int lane = tid & 31;
    int kh = tid >> 7, jl = tid & 127;

    __shared__ float  s1t[Dn][4];     // e1 normalized, k-major: [k][row]
    __shared__ float  s_r[4][2];
    __shared__ float4 s_acc[128];     // kh=1 partial {a0..a3}
    __shared__ float  s_ssq[128];     // kh=1 partial ssq

    // normalize e1: row = tid>>6, 64 threads (2 warps) per row, float4 each
    {
        int row = tid >> 6;
        int c   = tid & 63;
        float4 v = ((const float4*)e1)[(i0 + row) * (Dn / 4) + c];
        float ss = v.x * v.x + v.y * v.y + v.z * v.z + v.w * v.w;
        for (int o = 16; o; o >>= 1) ss += __shfl_down_sync(0xffffffffu, ss, o);
        if (lane == 0) s_r[row][(tid >> 5) & 1] = ss;
        __syncthreads();
        float inv = rsqrtf(s_r[row][0] + s_r[row][1]);
        s1t[c * 4 + 0][row] = v.x * inv;
        s1t[c * 4 + 1][row] = v.y * inv;
        s1t[c * 4 + 2][row] = v.z * inv;
        s1t[c * 4 + 3][row] = v.w * inv;
    }
    __syncthreads();

    // main loop: 128 k per half
    const float* bp = g_e2T + (kh * 128) * T2n + (j0 + jl);
    const float4* a4 = (const float4*)(&s1t[kh * 128][0]);
    float a0 = 0.f, a1 = 0.f, a2 = 0.f, a3 = 0.f, ssq = 0.f;
    #pragma unroll 8
    for (int k = 0; k < 128; k++) {
        float  b = bp[k * T2n];          // coalesced LDG (L2-resident)
        float4 a = a4[k];                // broadcast LDS.128: rows 0..3 at col k
        a0 = fmaf(a.x, b, a0);
        a1 = fmaf(a.y, b, a1);
        a2 = fmaf(a.z, b, a2);
        a3 = fmaf(a.w, b, a3);
        ssq = fmaf(b, b, ssq);
    }

    if (kh == 1) {
        s_acc[jl] = make_float4(a0, a1, a2, a3);
        s_ssq[jl] = ssq;
    }
    __syncthreads();
    if (kh == 0) {
        float4 p = s_acc[jl];
        float invj = rsqrtf(ssq + s_ssq[jl]);
        int j = j0 + jl;
        g_val[(i0 + 0) * T2n + j] = (a0 + p.x) * invj;
        g_val[(i0 + 1) * T2n + j] = (a1 + p.y) * invj;
        g_val[(i0 + 2) * T2n + j] = (a2 + p.z) * invj;
        g_val[(i0 + 3) * T2n + j] = (a3 + p.w) * invj;
    }
}

// ---------------------------------------------------------------------------
// K2: build. Grid 128 (block per i); 512 threads (16 warps).  (unchanged)
// ---------------------------------------------------------------------------
__global__ __launch_bounds__(512) void k_build(const int* __restrict__ sta,
                                               const int* __restrict__ pos,
                                               const unsigned* __restrict__ mask) {
    int i = blockIdx.x;
    int tid = threadIdx.x;
    int lane = tid & 31, w = tid >> 5;
    unsigned lt = (1u << lane) - 1u;

    __shared__ uint2 s_all[TPn][T2n];     // 32 KB
    __shared__ int   s_cm[TPn][16][16];   // [t][warp][bucket] counts -> offsets
    __shared__ int   s_bs[TPn][17];
    __shared__ int   s_st[TPn];
    __shared__ float s_red[16][9];

    if (tid < TPn) s_st[tid] = sta[i * TPn + tid];
    #pragma unroll
    for (int u = 0; u < 4; u++) ((int*)s_cm)[tid + 512 * u] = 0;
    __syncthreads();

    int j = tid;
    int4 p0 = ((const int4*)pos)[j * 2];
    int4 p1 = ((const int4*)pos)[j * 2 + 1];
    int pv[TPn] = {p0.x, p0.y, p0.z, p0.w, p1.x, p1.y, p1.z, p1.w};
    bool m = (mask[i * T2n + j] != 0u);
    float val = g_val[i * T2n + j];

    float dis[TPn];
    int   ab[TPn];
    float dsum = 0.f;
    #pragma unroll
    for (int tt = 0; tt < TPn; tt++) {
        int stt = s_st[tt];
        int a = stt < 0 ? -stt : stt;
        int b = pv[tt] < 0 ? -pv[tt] : pv[tt];
        ab[tt] = b;
        float sg = ((stt ^ pv[tt]) < 0) ? -1.0f : 1.0f;
        int v = (a ^ b) + 1;
        int p; asm("bfind.u32 %0, %1;" : "=r"(p) : "r"(v));
        float d = sg * (float)(15 - p) * (1.0f / 16.0f);
        dis[tt] = d;
        dsum += d;
    }

    {
        float red9[9];
        float B = dsum * 0.125f - val;
        red9[8] = m ? B * B : 0.0f;
        #pragma unroll
        for (int tt = 0; tt < TPn; tt++) {
            float A = (dsum - dis[tt]) * 0.125f - val;
            red9[tt] = m ? A * A : 0.0f;
        }
        #pragma unroll
        for (int o = 16; o; o >>= 1) {
            #pragma unroll
            for (int x = 0; x < 9; x++)
                red9[x] += __shfl_down_sync(0xffffffffu, red9[x], o);
        }
        if (lane == 0) {
            #pragma unroll
            for (int x = 0; x < 9; x++) s_red[w][x] = red9[x];
        }
    }

    unsigned ball = __ballot_sync(0xffffffffu, m);
    int rank[TPn];
    #pragma unroll
    for (int tt = 0; tt < TPn; tt++) {
        int b = ab[tt] >> 12;
        unsigned same = __match_any_sync(0xffffffffu, b) & ball;
        rank[tt] = __popc(same & lt);
        if (m && rank[tt] == 0) s_cm[tt][w][b] = __popc(same);
    }
    __syncthreads();

    if (w < TPn) {
        int t = w, b = lane & 15;
        int tot = 0;
        #pragma unroll
        for (int ww = 0; ww < 16; ww++) tot += s_cm[t][ww][b];
        int run = tot;
        #pragma unroll
        for (int o = 1; o < 16; o <<= 1) {
            int n = __shfl_up_sync(0xffffffffu, run, o, 16);
            if ((lane & 15) >= o) run += n;
        }
        if (lane < 16) {
            int excl = run - tot;
            s_bs[t][b] = excl;
            if (b == 15) s_bs[t][16] = run;
            int acc = excl;
            #pragma unroll
            for (int ww = 0; ww < 16; ww++) {
                int c = s_cm[t][ww][b]; s_cm[t][ww][b] = acc; acc += c;
            }
        }
    }
    if (tid >= 288 && tid < 297) {
        int x = tid - 288;
        float s = 0.f;
        #pragma unroll
        for (int ww = 0; ww < 16; ww++) s += s_red[ww][x];
        if (x < 8) g_SA[i * TPn + x] = s;
        else       g_L64[i] = s;
    }
    __syncthreads();

    if (m) {
        #pragma unroll
        for (int tt = 0; tt < TPn; tt++) {
            float A = (dsum - dis[tt]) * 0.125f - val;
            unsigned awb = __float_as_uint(A * (1.0f / 128.0f)) ^
                           ((unsigned)pv[tt] & 0x80000000u);
            int slot = s_cm[tt][w][ab[tt] >> 12] + rank[tt];
            s_all[tt][slot] = make_uint2(awb, (unsigned)ab[tt]);
        }
    }
    __syncthreads();

    {
        int unit = tid >> 2, q4 = tid & 3;
        int t = unit >> 4, b = unit & 15;
        int lo = s_bs[t][b], hi = s_bs[t][b + 1];
        float ws = 0.f;
        for (int k = lo + q4; k < hi; k += 4) ws += __uint_as_float(s_all[t][k].x);
        ws += __shfl_down_sync(0xffffffffu, ws, 2, 4);
        ws += __shfl_down_sync(0xffffffffu, ws, 1, 4);
        if (q4 == 0)
            g_WN[(i * TPn + t) * 16 + b] = make_float2(ws, (float)(hi - lo));
    }
    int cnt = s_bs[0][16];
    #pragma unroll
    for (int tt = 0; tt < TPn; tt++) {
        if (tid < cnt)
            g_pack[(i * TPn + tt) * T2n + tid] = s_all[tt][tid];
    }
    if (tid < TPn * 17) {
        int t = tid / 17, x = tid % 17;
        g_bs[(i * TPn + t) * 17 + x] = s_bs[t][x];
    }
}

// ---------------------------------------------------------------------------
// K3: loss. Grid (i,t) = (128,8); 256 threads; 4 threads/candidate. (unchanged)
// ---------------------------------------------------------------------------
__device__ __forceinline__ int make_cand(int c, int stav, const int* rm, int i, int t) {
    int h = c >> 2, k = c & 3;
    int r = rm[((i * Hn + h) * Kn + k) * TPn + t];
    return (stav ^ (1 << h)) ^ (r & ((1 << h) - 1));
}

__global__ __launch_bounds__(256, 6) void k_loss(const int* __restrict__ sta,
                                                 const int* __restrict__ rmask,
                                                 float* __restrict__ out) {
    int i = blockIdx.x, t = blockIdx.y;
    int tid = threadIdx.x;

    __shared__ uint2    s_pk[T2n];       // 4 KB
    __shared__ unsigned s_bm[2048];      // 8 KB presence bitmap over ap
    __shared__ int      s_bs[17];
    __shared__ float2   s_WN[16];

    int base = (i * TPn + t);
    if (tid < 17) s_bs[tid] = g_bs[base * 17 + tid];
    else if (tid >= 32 && tid < 48) s_WN[tid - 32] = g_WN[base * 16 + tid - 32];
    #pragma unroll
    for (int u = 0; u < 8; u++) s_bm[tid + 256 * u] = 0u;
    int cnt = __ldg(&g_bs[base * 17 + 16]);
    __syncthreads();

    const uint2* gp = g_pack + base * T2n;
    for (int idx = tid; idx < cnt; idx += 256) {
        uint2 e = gp[idx];
        s_pk[idx] = e;
        atomicOr(&s_bm[e.y >> 5], 1u << (e.y & 31));
    }
    __syncthreads();

    int c  = tid >> 2;                  // 0..63
    int q4 = tid & 3;
    int stav = sta[i * TPn + t];
    int cand = make_cand(c, stav, rmask, i, t);
    unsigned ac = (unsigned)(cand < 0 ? -cand : cand);
    int acH = (int)(ac >> 12);          // 0..16

    float S2 = 0.f, Sq = 0.f;

    #pragma unroll
    for (int u = 0; u < 4; u++) {
        int b = q4 * 4 + u;
        if (b != acH) {
            int xh = acH ^ b;
            int mb; asm("bfind.u32 %0, %1;" : "=r"(mb) : "r"(xh));
            float f = 8388611.0f - __int_as_float(mb | 0x4B000000);   // 3 - mb
            float2 wn = s_WN[b];
            S2 = fmaf(wn.x, f, S2);
            Sq = fmaf(wn.y, f * f, Sq);
        }
    }

    if (acH < 16) {
        int hi = s_bs[acH + 1];
        for (int k = s_bs[acH] + q4; k < hi; k += 4) {
            uint2 e = s_pk[k];
            unsigned v = (ac ^ e.y) + 1u;
            int qq; asm("bfind.u32 %0, %1;" : "=r"(qq) : "r"(v));
            float f = 8388623.0f - __int_as_float(qq | 0x4B000000);   // 15 - qq
            S2 = fmaf(__uint_as_float(e.x), f, S2);
            Sq = fmaf(f, f, Sq);
        }
    }

    #pragma unroll
    for (int pp = 0; pp < 2; pp++) {
        int kk = (pp == 0) ? (13 + q4) : 17;
        if (pp == 1 && q4 != 0) break;
        unsigned rv = ac ^ ((1u << kk) - 1u);
        if (rv <= 65535u) {
            if (s_bm[rv >> 5] & (1u << (rv & 31))) {
                int bb = (int)(rv >> 12);
                int lo = s_bs[bb], hi = s_bs[bb + 1];
                float dq = (float)(2 * kk - 31);
                for (int k = lo; k < hi; k++) {
                    uint2 e = s_pk[k];
                    if (e.y == rv) { S2 -= __uint_as_float(e.x); Sq += dq; }
                }
            }
        }
    }

    S2 += __shfl_down_sync(0xffffffffu, S2, 2, 4);
    S2 += __shfl_down_sync(0xffffffffu, S2, 1, 4);
    Sq += __shfl_down_sync(0xffffffffu, Sq, 2, 4);
    Sq += __shfl_down_sync(0xffffffffu, Sq, 1, 4);

    if (q4 == 0) {
        float SA = g_SA[base];
        float bse = SA + Sq * (1.0f / 16384.0f);
        float sc  = cand < 0 ? -1.0f : 1.0f;
        float tw  = 2.0f * sc * S2;
        float lp  = bse + tw;
        out[(i * Cn + c) * TPn + t] = lp;
        out[(i * Cn + 65 + c) * TPn + t] = (cand == 0) ? lp : (bse - tw);
    }
    if (tid == 0)
        out[(i * Cn + 64) * TPn + t] = g_L64[i];
}

// ---------------------------------------------------------------------------
extern "C" void kernel_launch(void* const* d_in, const int* in_sizes, int n_in,
                              void* d_out, int out_size) {
    const float*    emb1 = (const float*)d_in[0];
    const float*    emb2 = (const float*)d_in[1];
    const int*      sta  = (const int*)d_in[2];
    const int*      pos  = (const int*)d_in[3];
    const unsigned* mask = (const unsigned*)d_in[4];
    const int*      rm   = (const int*)d_in[5];
    float*          out  = (float*)d_out;

    dim3 tb(32, 8);
    k_t2<<<dim3(16, 8), tb>>>(emb2);
    k_val<<<dim3(32, 4), 256>>>(emb1);
    k_build<<<T1n, 512>>>(sta, pos, mask);
    k_loss<<<dim3(T1n, TPn), 256>>>(sta, rm, out);
}

// round 13
// speedup vs baseline: 2.1291x; 2.1291x over previous
#include <cuda_runtime.h>
#include <cuda_bf16.h>
#include <cstdint>

// ---- problem constants ----
#define T1n 128
#define T2n 512
#define TPn 8
#define Hn  16
#define Kn  4
#define Cn  129   // 2*K*H+1
#define Dn  256

// ---- device scratch ----
__device__ float  g_val[T1n * T2n];
__device__ uint2  g_pack[T1n * TPn * T2n];    // bucket-sorted compacted {awb, ap}
__device__ int    g_bs[T1n * TPn * 17];       // bucket starts (bs[16] = cnt)
__device__ float2 g_WN[T1n * TPn * 16];       // per-bucket {sum aw, (float)count}
__device__ float  g_SA[T1n * TPn];            // sum m*A^2
__device__ float  g_L64[T1n];                 // loss for c == sta

// ---------------------------------------------------------------------------
// K1: val_v[i][j] = <e1_i/|e1_i|, e2_j/|e2_j|>.
//   Grid (16,16); 64 threads. Block = 8 i-rows x 32 j-cols.
//   Both tiles staged ONCE into k-major smem, normalized at store time.
//   Inner loop: LDS.128 broadcast (4 i-vals) + conflict-free LDS b + 4 FMA.
//   No global accesses in the loop; no epilogue normalization.
// ---------------------------------------------------------------------------
__global__ __launch_bounds__(64) void k_val(const float* __restrict__ e1,
                                            const float* __restrict__ e2) {
    int i0 = blockIdx.x * 8;     // 16 i-tiles
    int j0 = blockIdx.y * 32;    // 16 j-tiles
    int tid = threadIdx.x;       // 64

    __shared__ float s_e1t[256][8];    // 8 KB  : [k][i-local], normalized
    __shared__ float s_e2t[256][32];   // 32 KB : [k][j-local], normalized

    // ---- e1 tile: 8 rows, 8 threads/row, 8 float4 each (coalesced 128B/row-seg)
    {
        int row = tid >> 3, c8 = tid & 7;
        const float4* rp = (const float4*)(e1 + (i0 + row) * Dn);
        float4 v[8];
        float ss = 0.f;
        #pragma unroll
        for (int u = 0; u < 8; u++) {
            v[u] = rp[c8 + 8 * u];
            ss = fmaf(v[u].x, v[u].x, ss); ss = fmaf(v[u].y, v[u].y, ss);
            ss = fmaf(v[u].z, v[u].z, ss); ss = fmaf(v[u].w, v[u].w, ss);
        }
        ss += __shfl_xor_sync(0xffffffffu, ss, 1, 8);
        ss += __shfl_xor_sync(0xffffffffu, ss, 2, 8);
        ss += __shfl_xor_sync(0xffffffffu, ss, 4, 8);
        float inv = rsqrtf(ss);
        #pragma unroll
        for (int u = 0; u < 8; u++) {
            int k = (c8 + 8 * u) * 4;
            s_e1t[k + 0][row] = v[u].x * inv;
            s_e1t[k + 1][row] = v[u].y * inv;
            s_e1t[k + 2][row] = v[u].z * inv;
            s_e1t[k + 3][row] = v[u].w * inv;
        }
    }
    // ---- e2 tile: 32 rows, 2 threads/row, 32 float4 each; two passes (regs low)
    {
        int row = tid >> 1, c2 = tid & 1;
        const float4* rp = (const float4*)(e2 + (j0 + row) * Dn);
        float ss = 0.f;
        #pragma unroll 8
        for (int u = 0; u < 32; u++) {
            float4 v = rp[c2 + 2 * u];
            ss = fmaf(v.x, v.x, ss); ss = fmaf(v.y, v.y, ss);
            ss = fmaf(v.z, v.z, ss); ss = fmaf(v.w, v.w, ss);
        }
        ss += __shfl_xor_sync(0xffffffffu, ss, 1, 2);
        float inv = rsqrtf(ss);
        #pragma unroll 8
        for (int u = 0; u < 32; u++) {
            float4 v = rp[c2 + 2 * u];          // L1 hit (pass 2)
            int k = (c2 + 2 * u) * 4;
            s_e2t[k + 0][row] = v.x * inv;
            s_e2t[k + 1][row] = v.y * inv;
            s_e2t[k + 2][row] = v.z * inv;
            s_e2t[k + 3][row] = v.w * inv;
        }
    }
    __syncthreads();

    // ---- main loop: thread = (ig = tid>>5 in {0,1}, jl = tid&31)
    int ig = tid >> 5;
    int jl = tid & 31;
    float a0 = 0.f, a1 = 0.f, a2 = 0.f, a3 = 0.f;
    #pragma unroll 8
    for (int k = 0; k < 256; k++) {
        float4 a = *(const float4*)&s_e1t[k][ig * 4];   // broadcast LDS.128
        float  b = s_e2t[k][jl];                        // conflict-free
        a0 = fmaf(a.x, b, a0);
        a1 = fmaf(a.y, b, a1);
        a2 = fmaf(a.z, b, a2);
        a3 = fmaf(a.w, b, a3);
    }
    int j = j0 + jl;
    g_val[(i0 + ig * 4 + 0) * T2n + j] = a0;
    g_val[(i0 + ig * 4 + 1) * T2n + j] = a1;
    g_val[(i0 + ig * 4 + 2) * T2n + j] = a2;
    g_val[(i0 + ig * 4 + 3) * T2n + j] = a3;
}

// ---------------------------------------------------------------------------
// K2: build. Grid 128 (block per i); 512 threads (16 warps).  (round-10 exact)
// ---------------------------------------------------------------------------
__global__ __launch_bounds__(512) void k_build(const int* __restrict__ sta,
                                               const int* __restrict__ pos,
                                               const unsigned* __restrict__ mask) {
    int i = blockIdx.x;
    int tid = threadIdx.x;
    int lane = tid & 31, w = tid >> 5;
    unsigned lt = (1u << lane) - 1u;

    __shared__ uint2 s_all[TPn][T2n];     // 32 KB
    __shared__ int   s_cm[TPn][16][16];   // [t][warp][bucket] counts -> offsets
    __shared__ int   s_bs[TPn][17];
    __shared__ int   s_st[TPn];
    __shared__ float s_red[16][9];

    if (tid < TPn) s_st[tid] = sta[i * TPn + tid];
    #pragma unroll
    for (int u = 0; u < 4; u++) ((int*)s_cm)[tid + 512 * u] = 0;
    __syncthreads();

    int j = tid;
    int4 p0 = ((const int4*)pos)[j * 2];
    int4 p1 = ((const int4*)pos)[j * 2 + 1];
    int pv[TPn] = {p0.x, p0.y, p0.z, p0.w, p1.x, p1.y, p1.z, p1.w};
    bool m = (mask[i * T2n + j] != 0u);
    float val = g_val[i * T2n + j];

    float dis[TPn];
    int   ab[TPn];
    float dsum = 0.f;
    #pragma unroll
    for (int tt = 0; tt < TPn; tt++) {
        int stt = s_st[tt];
        int a = stt < 0 ? -stt : stt;
        int b = pv[tt] < 0 ? -pv[tt] : pv[tt];
        ab[tt] = b;
        float sg = ((stt ^ pv[tt]) < 0) ? -1.0f : 1.0f;
        int v = (a ^ b) + 1;
        int p; asm("bfind.u32 %0, %1;" : "=r"(p) : "r"(v));
        float d = sg * (float)(15 - p) * (1.0f / 16.0f);
        dis[tt] = d;
        dsum += d;
    }

    {
        float red9[9];
        float B = dsum * 0.125f - val;
        red9[8] = m ? B * B : 0.0f;
        #pragma unroll
        for (int tt = 0; tt < TPn; tt++) {
            float A = (dsum - dis[tt]) * 0.125f - val;
            red9[tt] = m ? A * A : 0.0f;
        }
        #pragma unroll
        for (int o = 16; o; o >>= 1) {
            #pragma unroll
            for (int x = 0; x < 9; x++)
                red9[x] += __shfl_down_sync(0xffffffffu, red9[x], o);
        }
        if (lane == 0) {
            #pragma unroll
            for (int x = 0; x < 9; x++) s_red[w][x] = red9[x];
        }
    }

    unsigned ball = __ballot_sync(0xffffffffu, m);
    int rank[TPn];
    #pragma unroll
    for (int tt = 0; tt < TPn; tt++) {
        int b = ab[tt] >> 12;
        unsigned same = __match_any_sync(0xffffffffu, b) & ball;
        rank[tt] = __popc(same & lt);
        if (m && rank[tt] == 0) s_cm[tt][w][b] = __popc(same);
    }
    __syncthreads();

    if (w < TPn) {
        int t = w, b = lane & 15;
        int tot = 0;
        #pragma unroll
        for (int ww = 0; ww < 16; ww++) tot += s_cm[t][ww][b];
        int run = tot;
        #pragma unroll
        for (int o = 1; o < 16; o <<= 1) {
            int n = __shfl_up_sync(0xffffffffu, run, o, 16);
            if ((lane & 15) >= o) run += n;
        }
        if (lane < 16) {
            int excl = run - tot;
            s_bs[t][b] = excl;
            if (b == 15) s_bs[t][16] = run;
            int acc = excl;
            #pragma unroll
            for (int ww = 0; ww < 16; ww++) {
                int c = s_cm[t][ww][b]; s_cm[t][ww][b] = acc; acc += c;
            }
        }
    }
    if (tid >= 288 && tid < 297) {
        int x = tid - 288;
        float s = 0.f;
        #pragma unroll
        for (int ww = 0; ww < 16; ww++) s += s_red[ww][x];
        if (x < 8) g_SA[i * TPn + x] = s;
        else       g_L64[i] = s;
    }
    __syncthreads();

    if (m) {
        #pragma unroll
        for (int tt = 0; tt < TPn; tt++) {
            float A = (dsum - dis[tt]) * 0.125f - val;
            unsigned awb = __float_as_uint(A * (1.0f / 128.0f)) ^
                           ((unsigned)pv[tt] & 0x80000000u);
            int slot = s_cm[tt][w][ab[tt] >> 12] + rank[tt];
            s_all[tt][slot] = make_uint2(awb, (unsigned)ab[tt]);
        }
    }
    __syncthreads();

    {
        int unit = tid >> 2, q4 = tid & 3;
        int t = unit >> 4, b = unit & 15;
        int lo = s_bs[t][b], hi = s_bs[t][b + 1];
        float ws = 0.f;
        for (int k = lo + q4; k < hi; k += 4) ws += __uint_as_float(s_all[t][k].x);
        ws += __shfl_down_sync(0xffffffffu, ws, 2, 4);
        ws += __shfl_down_sync(0xffffffffu, ws, 1, 4);
        if (q4 == 0)
            g_WN[(i * TPn + t) * 16 + b] = make_float2(ws, (float)(hi - lo));
    }
    int cnt = s_bs[0][16];
    #pragma unroll
    for (int tt = 0; tt < TPn; tt++) {
        if (tid < cnt)
            g_pack[(i * TPn + tt) * T2n + tid] = s_all[tt][tid];
    }
    if (tid < TPn * 17) {
        int t = tid / 17, x = tid % 17;
        g_bs[(i * TPn + t) * 17 + x] = s_bs[t][x];
    }
}

// ---------------------------------------------------------------------------
// K3: loss. Grid (i,t) = (128,8); 256 threads; 4 threads/candidate. (round-10 exact)
// ---------------------------------------------------------------------------
__device__ __forceinline__ int make_cand(int c, int stav, const int* rm, int i, int t) {
    int h = c >> 2, k = c & 3;
    int r = rm[((i * Hn + h) * Kn + k) * TPn + t];
    return (stav ^ (1 << h)) ^ (r & ((1 << h) - 1));
}

__global__ __launch_bounds__(256, 6) void k_loss(const int* __restrict__ sta,
                                                 const int* __restrict__ rmask,
                                                 float* __restrict__ out) {
    int i = blockIdx.x, t = blockIdx.y;
    int tid = threadIdx.x;

    __shared__ uint2    s_pk[T2n];       // 4 KB
    __shared__ unsigned s_bm[2048];      // 8 KB presence bitmap over ap
    __shared__ int      s_bs[17];
    __shared__ float2   s_WN[16];

    int base = (i * TPn + t);
    if (tid < 17) s_bs[tid] = g_bs[base * 17 + tid];
    else if (tid >= 32 && tid < 48) s_WN[tid - 32] = g_WN[base * 16 + tid - 32];
    #pragma unroll
    for (int u = 0; u < 8; u++) s_bm[tid + 256 * u] = 0u;
    int cnt = __ldg(&g_bs[base * 17 + 16]);
    __syncthreads();

    const uint2* gp = g_pack + base * T2n;
    for (int idx = tid; idx < cnt; idx += 256) {
        uint2 e = gp[idx];
        s_pk[idx] = e;
        atomicOr(&s_bm[e.y >> 5], 1u << (e.y & 31));
    }
    __syncthreads();

    int c  = tid >> 2;                  // 0..63
    int q4 = tid & 3;
    int stav = sta[i * TPn + t];
    int cand = make_cand(c, stav, rmask, i, t);
    unsigned ac = (unsigned)(cand < 0 ? -cand : cand);
    int acH = (int)(ac >> 12);          // 0..16

    float S2 = 0.f, Sq = 0.f;

    #pragma unroll
    for (int u = 0; u < 4; u++) {
        int b = q4 * 4 + u;
        if (b != acH) {
            int xh = acH ^ b;
            int mb; asm("bfind.u32 %0, %1;" : "=r"(mb) : "r"(xh));
            float f = 8388611.0f - __int_as_float(mb | 0x4B000000);   // 3 - mb
            float2 wn = s_WN[b];
            S2 = fmaf(wn.x, f, S2);
            Sq = fmaf(wn.y, f * f, Sq);
        }
    }

    if (acH < 16) {
        int hi = s_bs[acH + 1];
        for (int k = s_bs[acH] + q4; k < hi; k += 4) {
            uint2 e = s_pk[k];
            unsigned v = (ac ^ e.y) + 1u;
            int qq; asm("bfind.u32 %0, %1;" : "=r"(qq) : "r"(v));
            float f = 8388623.0f - __int_as_float(qq | 0x4B000000);   // 15 - qq
            S2 = fmaf(__uint_as_float(e.x), f, S2);
            Sq = fmaf(f, f, Sq);
        }
    }

    #pragma unroll
    for (int pp = 0; pp < 2; pp++) {
        int kk = (pp == 0) ? (13 + q4) : 17;
        if (pp == 1 && q4 != 0) break;
        unsigned rv = ac ^ ((1u << kk) - 1u);
        if (rv <= 65535u) {
            if (s_bm[rv >> 5] & (1u << (rv & 31))) {
                int bb = (int)(rv >> 12);
                int lo = s_bs[bb], hi = s_bs[bb + 1];
                float dq = (float)(2 * kk - 31);
                for (int k = lo; k < hi; k++) {
                    uint2 e = s_pk[k];
                    if (e.y == rv) { S2 -= __uint_as_float(e.x); Sq += dq; }
                }
            }
        }
    }

    S2 += __shfl_down_sync(0xffffffffu, S2, 2, 4);
    S2 += __shfl_down_sync(0xffffffffu, S2, 1, 4);
    Sq += __shfl_down_sync(0xffffffffu, Sq, 2, 4);
    Sq += __shfl_down_sync(0xffffffffu, Sq, 1, 4);

    if (q4 == 0) {
        float SA = g_SA[base];
        float bse = SA + Sq * (1.0f / 16384.0f);
        float sc  = cand < 0 ? -1.0f : 1.0f;
        float tw  = 2.0f * sc * S2;
        float lp  = bse + tw;
        out[(i * Cn + c) * TPn + t] = lp;
        out[(i * Cn + 65 + c) * TPn + t] = (cand == 0) ? lp : (bse - tw);
    }
    if (tid == 0)
        out[(i * Cn + 64) * TPn + t] = g_L64[i];
}

// ---------------------------------------------------------------------------
extern "C" void kernel_launch(void* const* d_in, const int* in_sizes, int n_in,
                              void* d_out, int out_size) {
    const float*    emb1 = (const float*)d_in[0];
    const float*    emb2 = (const float*)d_in[1];
    const int*      sta  = (const int*)d_in[2];
    const int*      pos  = (const int*)d_in[3];
    const unsigned* mask = (const unsigned*)d_in[4];
    const int*      rm   = (const int*)d_in[5];
    float*          out  = (float*)d_out;

    k_val<<<dim3(16, 16), 64>>>(emb1, emb2);
    k_build<<<T1n, 512>>>(sta, pos, mask);
    k_loss<<<dim3(T1n, TPn), 256>>>(sta, rm, out);
}